// round 1
// baseline (speedup 1.0000x reference)
#include <cuda_runtime.h>
#include <math.h>

#define BB 32
#define NN 256
#define HH 12
#define DD 64
#define CC 768

// ---------------- scratch (device globals; no runtime allocation) ----------------
__device__ float g_qin[BB*HH*NN*DD];     // (b,h,n,d)
__device__ float g_kin[BB*HH*NN*DD];     // (b,h,n,d)
__device__ float g_v  [BB*HH*NN*DD];     // (b,h,n,d)
__device__ float g_qgr[BB*NN*CC];        // (b,n,h*64+d)
__device__ float g_kgr[BB*NN*CC];        // (b,n,h*64+d)
__device__ float g_mix[(size_t)BB*HH*NN*NN]; // (b,o,n,m)
__device__ float g_ctx[BB*NN*CC];        // (b,n,h*64+d)

// =====================================================================
// GEMM 1: qkv = x @ qkv_w^T + qkv_b ; scatter into q/k/v head layouts
// C[i][j], M=8192, N=2304, K=768. A row-major, W row-major (N x K).
// =====================================================================
__global__ void gemm_qkv_kernel(const float* __restrict__ X,
                                const float* __restrict__ W,
                                const float* __restrict__ bias)
{
    __shared__ float As[16][65];
    __shared__ float Bs[16][65];
    const int K = 768;
    int tid = threadIdx.x;
    int bm = blockIdx.y * 64;   // row tile
    int bn = blockIdx.x * 64;   // col tile
    int ty = tid >> 4, tx = tid & 15;
    int lr = tid >> 2;          // 0..63
    int lc = (tid & 3) * 4;     // 0,4,8,12

    float acc[4][4];
#pragma unroll
    for (int i = 0; i < 4; i++)
#pragma unroll
        for (int j = 0; j < 4; j++) acc[i][j] = 0.f;

    for (int kt = 0; kt < K; kt += 16) {
        float4 a4 = *(const float4*)(X + (size_t)(bm + lr) * K + kt + lc);
        float4 b4 = *(const float4*)(W + (size_t)(bn + lr) * K + kt + lc);
        As[lc + 0][lr] = a4.x; As[lc + 1][lr] = a4.y; As[lc + 2][lr] = a4.z; As[lc + 3][lr] = a4.w;
        Bs[lc + 0][lr] = b4.x; Bs[lc + 1][lr] = b4.y; Bs[lc + 2][lr] = b4.z; Bs[lc + 3][lr] = b4.w;
        __syncthreads();
#pragma unroll
        for (int k = 0; k < 16; k++) {
            float a[4], b[4];
#pragma unroll
            for (int i = 0; i < 4; i++) a[i] = As[k][ty * 4 + i];
#pragma unroll
            for (int j = 0; j < 4; j++) b[j] = Bs[k][tx * 4 + j];
#pragma unroll
            for (int i = 0; i < 4; i++)
#pragma unroll
                for (int j = 0; j < 4; j++) acc[i][j] += a[i] * b[j];
        }
        __syncthreads();
    }

#pragma unroll
    for (int i = 0; i < 4; i++) {
        int row = bm + ty * 4 + i;
        int b = row >> 8, n = row & 255;
#pragma unroll
        for (int j = 0; j < 4; j++) {
            int col = bn + tx * 4 + j;
            float val = acc[i][j] + bias[col];
            int which = col / 768;
            int r = col % 768;
            int h = r >> 6, dd = r & 63;
            float* dst = (which == 0) ? g_qin : (which == 1) ? g_kin : g_v;
            dst[(((size_t)(b * 12 + h) * 256) + n) * 64 + dd] = val;
        }
    }
}

// =====================================================================
// Batched Householder QR (LAPACK sgeqrf + sorg2r convention).
// One block per slab (768 slabs: 384 q + 384 k). Slab is 256x64.
// Shared: column-major with pad 257 for conflict-free access.
// =====================================================================
__global__ void qr_kernel()
{
    extern __shared__ float sA[];   // 64 * 257
    __shared__ float s_tau[64];
    __shared__ float s_red[8];

    const int tid = threadIdx.x;
    const int lane = tid & 31, warp = tid >> 5;

    int slab = blockIdx.x;
    int isk = (slab >= 384) ? 1 : 0;
    int s = slab - isk * 384;
    const float* src = (isk ? g_kin : g_qin) + (size_t)s * NN * DD;
    float* dst = isk ? g_kgr : g_qgr;
    int b = s / 12, h = s % 12;

    for (int idx = tid; idx < NN * DD; idx += 256) {
        int r = idx >> 6, c = idx & 63;
        sA[c * 257 + r] = src[idx];
    }
    __syncthreads();

    // ---------------- geqrf ----------------
    for (int j = 0; j < 64; j++) {
        float* colj = sA + j * 257;
        float x = (tid >= j) ? colj[tid] : 0.f;
        float ss = x * x;
#pragma unroll
        for (int o = 16; o > 0; o >>= 1) ss += __shfl_xor_sync(0xffffffffu, ss, o);
        if (lane == 0) s_red[warp] = ss;
        __syncthreads();
        float tot = 0.f;
#pragma unroll
        for (int w = 0; w < 8; w++) tot += s_red[w];
        float alpha = colj[j];
        float norm = sqrtf(tot);
        float tau, scal;
        if (norm < 1e-30f) { tau = 0.f; scal = 0.f; }
        else {
            float beta = (alpha >= 0.f) ? -norm : norm;
            tau = (beta - alpha) / beta;
            scal = 1.f / (alpha - beta);
        }
        if (tid == 0) s_tau[j] = tau;
        __syncthreads();                 // all reads of colj done before writes
        if (tid > j)       colj[tid] *= scal;   // store v (v_j = 1)
        else if (tid == j) colj[tid] = 1.f;
        __syncthreads();
        // trailing update: warp-per-column
        for (int c = j + 1 + warp; c < 64; c += 8) {
            float* colc = sA + c * 257;
            float dt = 0.f;
            for (int r = lane; r < 256; r += 32)
                if (r >= j) dt += colj[r] * colc[r];
#pragma unroll
            for (int o = 16; o > 0; o >>= 1) dt += __shfl_xor_sync(0xffffffffu, dt, o);
            float w = tau * dt;
            for (int r = lane; r < 256; r += 32)
                if (r >= j) colc[r] -= w * colj[r];
        }
        __syncthreads();
    }

    // ---------------- org2r (in place) ----------------
    for (int i = 63; i >= 0; i--) {
        float* coli = sA + i * 257;
        float tau = s_tau[i];
        for (int c = i + 1 + warp; c < 64; c += 8) {
            float* colc = sA + c * 257;
            float dt = 0.f;
            for (int r = lane; r < 256; r += 32)
                if (r >= i) dt += coli[r] * colc[r];
#pragma unroll
            for (int o = 16; o > 0; o >>= 1) dt += __shfl_xor_sync(0xffffffffu, dt, o);
            float w = tau * dt;
            for (int r = lane; r < 256; r += 32)
                if (r >= i) colc[r] -= w * coli[r];
        }
        __syncthreads();
        float v = coli[tid];
        float nv;
        if (tid < i)       nv = 0.f;
        else if (tid == i) nv = 1.f - tau;
        else               nv = -tau * v;
        coli[tid] = nv;
        __syncthreads();
    }

    // writeout to (b, n, h*64 + d)
    for (int idx = tid; idx < NN * DD; idx += 256) {
        int r = idx >> 6, c = idx & 63;
        dst[(size_t)(b * 256 + r) * 768 + h * 64 + c] = sA[c * 257 + r];
    }
}

// =====================================================================
// dots^2 + channel mix:
// mixed[b,o,n,m] = conv_b[o] + sum_h (cw[o,h]+cw[o,h+12]) * gs * (qgr[b,n,h,:].kgr[b,m,h,:])^2
// Block: 32x32 (n,m) tile for one b; 256 threads, 2x2 per thread.
// =====================================================================
__global__ void dotmix_kernel(const float* __restrict__ conv_w,
                              const float* __restrict__ conv_b,
                              const float* __restrict__ gscale)
{
    __shared__ float sq[32][65], sk[32][65];
    __shared__ float s_w2[12][12];
    __shared__ float s_cb[12];
    __shared__ float s_gs;

    int tid = threadIdx.x;
    int b = blockIdx.z;
    int nbase = blockIdx.y * 32, mbase = blockIdx.x * 32;

    if (tid < 144) {
        int o = tid / 12, hh = tid % 12;
        s_w2[o][hh] = conv_w[o * 24 + hh] + conv_w[o * 24 + 12 + hh];
    }
    if (tid < 12) s_cb[tid] = conv_b[tid];
    if (tid == 0) s_gs = gscale[0];

    int ty = tid >> 4, tx = tid & 15;
    float outacc[12][4];
#pragma unroll
    for (int o = 0; o < 12; o++)
#pragma unroll
        for (int p = 0; p < 4; p++) outacc[o][p] = 0.f;

    for (int h = 0; h < 12; h++) {
        __syncthreads();
        for (int idx = tid; idx < 2048; idx += 256) {
            int r = idx >> 6, d = idx & 63;
            sq[r][d] = g_qgr[(size_t)(b * 256 + nbase + r) * 768 + h * 64 + d];
            sk[r][d] = g_kgr[(size_t)(b * 256 + mbase + r) * 768 + h * 64 + d];
        }
        __syncthreads();
        float d0 = 0.f, d1 = 0.f, d2 = 0.f, d3 = 0.f;
#pragma unroll
        for (int d = 0; d < 64; d++) {
            float q0 = sq[ty * 2][d], q1 = sq[ty * 2 + 1][d];
            float k0 = sk[tx * 2][d], k1 = sk[tx * 2 + 1][d];
            d0 += q0 * k0; d1 += q0 * k1; d2 += q1 * k0; d3 += q1 * k1;
        }
        float gs = s_gs;
        float s0 = d0 * d0 * gs, s1 = d1 * d1 * gs, s2 = d2 * d2 * gs, s3 = d3 * d3 * gs;
#pragma unroll
        for (int o = 0; o < 12; o++) {
            float w = s_w2[o][h];
            outacc[o][0] += w * s0; outacc[o][1] += w * s1;
            outacc[o][2] += w * s2; outacc[o][3] += w * s3;
        }
    }

#pragma unroll
    for (int p = 0; p < 4; p++) {
        int n = nbase + ty * 2 + (p >> 1);
        int m = mbase + tx * 2 + (p & 1);
#pragma unroll
        for (int o = 0; o < 12; o++) {
            g_mix[((size_t)(b * 12 + o) * 256 + n) * 256 + m] = outacc[o][p] + s_cb[o];
        }
    }
}

// =====================================================================
// softmax over last dim (rows of length 256). Warp per row, 8 rows/block.
// =====================================================================
__global__ void softmax_kernel()
{
    int warp = threadIdx.x >> 5, lane = threadIdx.x & 31;
    size_t row = (size_t)blockIdx.x * 8 + warp;
    float* p = g_mix + row * 256;
    float4 v0 = ((float4*)p)[lane];
    float4 v1 = ((float4*)p)[lane + 32];
    float mx = fmaxf(fmaxf(fmaxf(v0.x, v0.y), fmaxf(v0.z, v0.w)),
                     fmaxf(fmaxf(v1.x, v1.y), fmaxf(v1.z, v1.w)));
#pragma unroll
    for (int o = 16; o > 0; o >>= 1) mx = fmaxf(mx, __shfl_xor_sync(0xffffffffu, mx, o));
    v0.x = expf(v0.x - mx); v0.y = expf(v0.y - mx); v0.z = expf(v0.z - mx); v0.w = expf(v0.w - mx);
    v1.x = expf(v1.x - mx); v1.y = expf(v1.y - mx); v1.z = expf(v1.z - mx); v1.w = expf(v1.w - mx);
    float sm = v0.x + v0.y + v0.z + v0.w + v1.x + v1.y + v1.z + v1.w;
#pragma unroll
    for (int o = 16; o > 0; o >>= 1) sm += __shfl_xor_sync(0xffffffffu, sm, o);
    float inv = 1.f / sm;
    v0.x *= inv; v0.y *= inv; v0.z *= inv; v0.w *= inv;
    v1.x *= inv; v1.y *= inv; v1.z *= inv; v1.w *= inv;
    ((float4*)p)[lane] = v0;
    ((float4*)p)[lane + 32] = v1;
}

// =====================================================================
// PV: per (b,h): C(256x64) = P(256x256) @ V(256x64), write to ctx (b,n,h*64+d)
// =====================================================================
__global__ void gemm_pv_kernel()
{
    __shared__ float Ps[16][65], Vs[16][65];
    int tid = threadIdx.x;
    int bh = blockIdx.y;
    int b = bh / 12, h = bh % 12;
    const float* P = g_mix + (size_t)bh * 65536;
    const float* V = g_v + (size_t)bh * 16384;
    int bm = blockIdx.x * 64;
    int ty = tid >> 4, tx = tid & 15;

    float acc[4][4];
#pragma unroll
    for (int i = 0; i < 4; i++)
#pragma unroll
        for (int j = 0; j < 4; j++) acc[i][j] = 0.f;

    for (int kt = 0; kt < 256; kt += 16) {
        float4 a4 = *(const float4*)(P + (size_t)(bm + (tid >> 2)) * 256 + kt + (tid & 3) * 4);
        int ac = (tid & 3) * 4, ar = tid >> 2;
        Ps[ac + 0][ar] = a4.x; Ps[ac + 1][ar] = a4.y; Ps[ac + 2][ar] = a4.z; Ps[ac + 3][ar] = a4.w;
        float4 b4 = *(const float4*)(V + (size_t)(kt + (tid >> 4)) * 64 + (tid & 15) * 4);
        int vk = tid >> 4, vn = (tid & 15) * 4;
        Vs[vk][vn + 0] = b4.x; Vs[vk][vn + 1] = b4.y; Vs[vk][vn + 2] = b4.z; Vs[vk][vn + 3] = b4.w;
        __syncthreads();
#pragma unroll
        for (int k = 0; k < 16; k++) {
            float a[4], bb[4];
#pragma unroll
            for (int i = 0; i < 4; i++) a[i] = Ps[k][ty * 4 + i];
#pragma unroll
            for (int j = 0; j < 4; j++) bb[j] = Vs[k][tx * 4 + j];
#pragma unroll
            for (int i = 0; i < 4; i++)
#pragma unroll
                for (int j = 0; j < 4; j++) acc[i][j] += a[i] * bb[j];
        }
        __syncthreads();
    }

#pragma unroll
    for (int i = 0; i < 4; i++) {
        int n = bm + ty * 4 + i;
#pragma unroll
        for (int j = 0; j < 4; j++) {
            int dd = tx * 4 + j;
            g_ctx[(size_t)(b * 256 + n) * 768 + h * 64 + dd] = acc[i][j];
        }
    }
}

// =====================================================================
// Final projection: out = ctx @ proj_w^T + proj_b.  M=8192,N=768,K=768
// =====================================================================
__global__ void gemm_proj_kernel(const float* __restrict__ W,
                                 const float* __restrict__ bias,
                                 float* __restrict__ out)
{
    __shared__ float As[16][65];
    __shared__ float Bs[16][65];
    const int K = 768;
    int tid = threadIdx.x;
    int bm = blockIdx.y * 64;
    int bn = blockIdx.x * 64;
    int ty = tid >> 4, tx = tid & 15;
    int lr = tid >> 2;
    int lc = (tid & 3) * 4;

    float acc[4][4];
#pragma unroll
    for (int i = 0; i < 4; i++)
#pragma unroll
        for (int j = 0; j < 4; j++) acc[i][j] = 0.f;

    for (int kt = 0; kt < K; kt += 16) {
        float4 a4 = *(const float4*)(g_ctx + (size_t)(bm + lr) * K + kt + lc);
        float4 b4 = *(const float4*)(W + (size_t)(bn + lr) * K + kt + lc);
        As[lc + 0][lr] = a4.x; As[lc + 1][lr] = a4.y; As[lc + 2][lr] = a4.z; As[lc + 3][lr] = a4.w;
        Bs[lc + 0][lr] = b4.x; Bs[lc + 1][lr] = b4.y; Bs[lc + 2][lr] = b4.z; Bs[lc + 3][lr] = b4.w;
        __syncthreads();
#pragma unroll
        for (int k = 0; k < 16; k++) {
            float a[4], b[4];
#pragma unroll
            for (int i = 0; i < 4; i++) a[i] = As[k][ty * 4 + i];
#pragma unroll
            for (int j = 0; j < 4; j++) b[j] = Bs[k][tx * 4 + j];
#pragma unroll
            for (int i = 0; i < 4; i++)
#pragma unroll
                for (int j = 0; j < 4; j++) acc[i][j] += a[i] * b[j];
        }
        __syncthreads();
    }

#pragma unroll
    for (int i = 0; i < 4; i++) {
        int row = bm + ty * 4 + i;
#pragma unroll
        for (int j = 0; j < 4; j++) {
            int col = bn + tx * 4 + j;
            out[(size_t)row * 768 + col] = acc[i][j] + bias[col];
        }
    }
}

// =====================================================================
extern "C" void kernel_launch(void* const* d_in, const int* in_sizes, int n_in,
                              void* d_out, int out_size)
{
    const float* x       = (const float*)d_in[0];
    const float* qkv_w   = (const float*)d_in[1];
    const float* qkv_b   = (const float*)d_in[2];
    const float* gscale  = (const float*)d_in[3];
    const float* conv_w  = (const float*)d_in[4];
    const float* conv_b  = (const float*)d_in[5];
    const float* proj_w  = (const float*)d_in[6];
    const float* proj_b  = (const float*)d_in[7];
    float* out = (float*)d_out;

    cudaFuncSetAttribute(qr_kernel, cudaFuncAttributeMaxDynamicSharedMemorySize, 64 * 257 * 4);

    gemm_qkv_kernel<<<dim3(36, 128), 256>>>(x, qkv_w, qkv_b);
    qr_kernel<<<768, 256, 64 * 257 * 4>>>();
    dotmix_kernel<<<dim3(8, 8, 32), 256>>>(conv_w, conv_b, gscale);
    softmax_kernel<<<12288, 256>>>();
    gemm_pv_kernel<<<dim3(4, 384), 256>>>();
    gemm_proj_kernel<<<dim3(12, 128), 256>>>(proj_w, proj_b, out);
}

// round 3
// speedup vs baseline: 2.0336x; 2.0336x over previous
#include <cuda_runtime.h>
#include <cstdint>
#include <math.h>

#define BB 32
#define NN 256
#define HH 12
#define DD 64
#define CC 768

// ---------------- scratch (device globals; no runtime allocation) ----------------
__device__ float g_qin[BB*HH*NN*DD];      // (b,h,n,d)
__device__ float g_kin[BB*HH*NN*DD];      // (b,h,n,d)
__device__ float g_vt [BB*HH*DD*NN];      // (b,h,d,m)  V transposed for PV GEMM
__device__ float g_qgr[BB*NN*CC];         // (b,n,h*64+d)
__device__ float g_kgr[BB*NN*CC];         // (b,n,h*64+d)
__device__ float g_sq [(size_t)BB*HH*NN*NN]; // gs*dots^2  (b,h,n,m)
__device__ float g_mix[(size_t)BB*HH*NN*NN]; // softmaxed P (b,o,n,m)
__device__ float g_ctx[BB*NN*CC];         // (b,n,h*64+d)

__device__ __forceinline__ float tf32_rna(float f) {
    uint32_t o;
    asm("cvt.rna.tf32.f32 %0, %1;" : "=r"(o) : "f"(f));
    return __uint_as_float(o);
}

__device__ __forceinline__ void mma_tf32(float* c, const float* a, const float* b) {
    asm volatile(
        "mma.sync.aligned.m16n8k8.row.col.f32.tf32.tf32.f32 "
        "{%0,%1,%2,%3}, {%4,%5,%6,%7}, {%8,%9}, {%0,%1,%2,%3};"
        : "+f"(c[0]), "+f"(c[1]), "+f"(c[2]), "+f"(c[3])
        : "r"(__float_as_uint(a[0])), "r"(__float_as_uint(a[1])),
          "r"(__float_as_uint(a[2])), "r"(__float_as_uint(a[3])),
          "r"(__float_as_uint(b[0])), "r"(__float_as_uint(b[1])));
}

// ======================= TF32 mma.sync GEMM =======================
// C[M,N] = A[M,K] @ B[N,K]^T  (both operands K-major per row)
// Block tile: 128 x TN, K-chunk 16. 8 warps in 4(m) x 2(n); warp tile 32 x TN/2.
// MODE 0: qkv = x @ qkv_w^T + b, scatter to q/k/vt
// MODE 1: dots per (b,h); epilogue sq = gs*dots^2
// MODE 2: PV per (b,h): P(256x256) @ Vt(64x256)^T -> ctx
// MODE 3: proj = ctx @ proj_w^T + b -> out
template<int MODE, int TN, int NCH>
__global__ void __launch_bounds__(256) gemm_mma(const float* __restrict__ Ain,
                                                const float* __restrict__ Bin,
                                                const float* __restrict__ Xtra,
                                                float* __restrict__ Og)
{
    __shared__ float As[128 * 20];
    __shared__ float Bs[TN * 20];
    constexpr int NF = TN / 16;            // n-fragments per warp
    constexpr int NB4 = (TN * 4) / 256;    // B float4 loads per thread (2 or 1)

    const int tid = threadIdx.x, lane = tid & 31, wid = tid >> 5;
    const int wm = wid >> 1, wn = wid & 1;

    const float* Aba; const float* Bba; int sA, sB;
    if (MODE == 0) {
        Aba = Ain + (size_t)blockIdx.y * 128 * 768; sA = 768;
        Bba = Bin + (size_t)blockIdx.x * 128 * 768; sB = 768;
    } else if (MODE == 1) {
        int b = blockIdx.z, h = blockIdx.y;
        int nt = blockIdx.x >> 1, mt = blockIdx.x & 1;
        Aba = g_qgr + ((size_t)(b * 256 + nt * 128)) * 768 + h * 64; sA = 768;
        Bba = g_kgr + ((size_t)(b * 256 + mt * 128)) * 768 + h * 64; sB = 768;
    } else if (MODE == 2) {
        Aba = g_mix + (size_t)blockIdx.y * 65536 + (size_t)blockIdx.x * 128 * 256; sA = 256;
        Bba = g_vt + (size_t)blockIdx.y * 16384; sB = 256;
    } else {
        Aba = g_ctx + (size_t)blockIdx.y * 128 * 768; sA = 768;
        Bba = Bin + (size_t)blockIdx.x * 128 * 768; sB = 768;
    }

    float c[2][NF][4];
#pragma unroll
    for (int mf = 0; mf < 2; mf++)
#pragma unroll
        for (int nf = 0; nf < NF; nf++)
#pragma unroll
            for (int e = 0; e < 4; e++) c[mf][nf][e] = 0.f;

    float4 ra[2], rb[NB4];

    // prologue loads
#pragma unroll
    for (int i = 0; i < 2; i++) {
        int f = tid + i * 256; int r = f >> 2, cc = (f & 3) * 4;
        ra[i] = *(const float4*)(Aba + (size_t)r * sA + cc);
    }
#pragma unroll
    for (int i = 0; i < NB4; i++) {
        int f = tid + i * 256; int r = f >> 2, cc = (f & 3) * 4;
        rb[i] = *(const float4*)(Bba + (size_t)r * sB + cc);
    }

    for (int ch = 0; ch < NCH; ch++) {
        // store (with tf32 rounding) to shared
#pragma unroll
        for (int i = 0; i < 2; i++) {
            int f = tid + i * 256; int r = f >> 2, cc = (f & 3) * 4;
            float4 v = ra[i];
            v.x = tf32_rna(v.x); v.y = tf32_rna(v.y); v.z = tf32_rna(v.z); v.w = tf32_rna(v.w);
            *(float4*)&As[r * 20 + cc] = v;
        }
#pragma unroll
        for (int i = 0; i < NB4; i++) {
            int f = tid + i * 256; int r = f >> 2, cc = (f & 3) * 4;
            float4 v = rb[i];
            v.x = tf32_rna(v.x); v.y = tf32_rna(v.y); v.z = tf32_rna(v.z); v.w = tf32_rna(v.w);
            *(float4*)&Bs[r * 20 + cc] = v;
        }
        __syncthreads();

        // issue next chunk's global loads (overlap with MMA)
        if (ch + 1 < NCH) {
            int ko = (ch + 1) * 16;
#pragma unroll
            for (int i = 0; i < 2; i++) {
                int f = tid + i * 256; int r = f >> 2, cc = (f & 3) * 4;
                ra[i] = *(const float4*)(Aba + (size_t)r * sA + ko + cc);
            }
#pragma unroll
            for (int i = 0; i < NB4; i++) {
                int f = tid + i * 256; int r = f >> 2, cc = (f & 3) * 4;
                rb[i] = *(const float4*)(Bba + (size_t)r * sB + ko + cc);
            }
        }

        // MMA over the 16-wide chunk (two k=8 sub-steps)
#pragma unroll
        for (int kk = 0; kk < 2; kk++) {
            const int ko = kk * 8;
            float a[2][4];
#pragma unroll
            for (int mf = 0; mf < 2; mf++) {
                int r0 = wm * 32 + mf * 16 + (lane >> 2);
                a[mf][0] = As[r0 * 20 + ko + (lane & 3)];
                a[mf][1] = As[(r0 + 8) * 20 + ko + (lane & 3)];
                a[mf][2] = As[r0 * 20 + ko + 4 + (lane & 3)];
                a[mf][3] = As[(r0 + 8) * 20 + ko + 4 + (lane & 3)];
            }
            float b[NF][2];
#pragma unroll
            for (int nf = 0; nf < NF; nf++) {
                int rr = wn * (TN / 2) + nf * 8 + (lane >> 2);
                b[nf][0] = Bs[rr * 20 + ko + (lane & 3)];
                b[nf][1] = Bs[rr * 20 + ko + 4 + (lane & 3)];
            }
#pragma unroll
            for (int mf = 0; mf < 2; mf++)
#pragma unroll
                for (int nf = 0; nf < NF; nf++)
                    mma_tf32(c[mf][nf], a[mf], b[nf]);
        }
        __syncthreads();
    }

    // ---------------- epilogue ----------------
#pragma unroll
    for (int mf = 0; mf < 2; mf++) {
#pragma unroll
        for (int nf = 0; nf < NF; nf++) {
            int rib0 = wm * 32 + mf * 16 + (lane >> 2);
            int cib = wn * (TN / 2) + nf * 8 + 2 * (lane & 3);
#pragma unroll
            for (int e = 0; e < 2; e++) {
                int rib = rib0 + e * 8;
                float v0 = c[mf][nf][e * 2], v1 = c[mf][nf][e * 2 + 1];
                if (MODE == 0) {
                    int colg = blockIdx.x * 128 + cib;
                    int rowg = blockIdx.y * 128 + rib;
                    int b = rowg >> 8, n = rowg & 255;
                    int which = colg / 768;
                    int rr = colg - which * 768;
                    int h = rr >> 6, dd = rr & 63;
                    v0 += Xtra[colg]; v1 += Xtra[colg + 1];
                    if (which == 0)
                        *(float2*)&g_qin[(((size_t)(b * 12 + h) * 256) + n) * 64 + dd] = make_float2(v0, v1);
                    else if (which == 1)
                        *(float2*)&g_kin[(((size_t)(b * 12 + h) * 256) + n) * 64 + dd] = make_float2(v0, v1);
                    else {
                        g_vt[(((size_t)(b * 12 + h)) * 64 + dd) * 256 + n] = v0;
                        g_vt[(((size_t)(b * 12 + h)) * 64 + dd + 1) * 256 + n] = v1;
                    }
                } else if (MODE == 1) {
                    float gs = Xtra[0];
                    int b = blockIdx.z, h = blockIdx.y;
                    int nt = blockIdx.x >> 1, mt = blockIdx.x & 1;
                    int n = nt * 128 + rib;
                    int m = mt * 128 + cib;
                    v0 = v0 * v0 * gs; v1 = v1 * v1 * gs;
                    *(float2*)&g_sq[(((size_t)(b * 12 + h) * 256) + n) * 256 + m] = make_float2(v0, v1);
                } else if (MODE == 2) {
                    int bh = blockIdx.y; int b = bh / 12, h = bh - b * 12;
                    int n = blockIdx.x * 128 + rib;
                    *(float2*)&g_ctx[((size_t)(b * 256 + n)) * 768 + h * 64 + cib] = make_float2(v0, v1);
                } else {
                    int colg = blockIdx.x * 128 + cib;
                    int rowg = blockIdx.y * 128 + rib;
                    v0 += Xtra[colg]; v1 += Xtra[colg + 1];
                    *(float2*)&Og[(size_t)rowg * 768 + colg] = make_float2(v0, v1);
                }
            }
        }
    }
}

// =====================================================================
// Batched Householder QR (LAPACK sgeqrf + sorg2r convention).
// =====================================================================
__global__ void qr_kernel()
{
    extern __shared__ float sA[];   // 64 * 257
    __shared__ float s_tau[64];
    __shared__ float s_red[8];

    const int tid = threadIdx.x;
    const int lane = tid & 31, warp = tid >> 5;

    int slab = blockIdx.x;
    int isk = (slab >= 384) ? 1 : 0;
    int s = slab - isk * 384;
    const float* src = (isk ? g_kin : g_qin) + (size_t)s * NN * DD;
    float* dst = isk ? g_kgr : g_qgr;
    int b = s / 12, h = s % 12;

    for (int idx = tid; idx < NN * DD; idx += 256) {
        int r = idx >> 6, c = idx & 63;
        sA[c * 257 + r] = src[idx];
    }
    __syncthreads();

    for (int j = 0; j < 64; j++) {
        float* colj = sA + j * 257;
        float x = (tid >= j) ? colj[tid] : 0.f;
        float ss = x * x;
#pragma unroll
        for (int o = 16; o > 0; o >>= 1) ss += __shfl_xor_sync(0xffffffffu, ss, o);
        if (lane == 0) s_red[warp] = ss;
        __syncthreads();
        float tot = 0.f;
#pragma unroll
        for (int w = 0; w < 8; w++) tot += s_red[w];
        float alpha = colj[j];
        float norm = sqrtf(tot);
        float tau, scal;
        if (norm < 1e-30f) { tau = 0.f; scal = 0.f; }
        else {
            float beta = (alpha >= 0.f) ? -norm : norm;
            tau = (beta - alpha) / beta;
            scal = 1.f / (alpha - beta);
        }
        if (tid == 0) s_tau[j] = tau;
        __syncthreads();
        if (tid > j)       colj[tid] *= scal;
        else if (tid == j) colj[tid] = 1.f;
        __syncthreads();
        for (int c = j + 1 + warp; c < 64; c += 8) {
            float* colc = sA + c * 257;
            float dt = 0.f;
            for (int r = lane; r < 256; r += 32)
                if (r >= j) dt += colj[r] * colc[r];
#pragma unroll
            for (int o = 16; o > 0; o >>= 1) dt += __shfl_xor_sync(0xffffffffu, dt, o);
            float w = tau * dt;
            for (int r = lane; r < 256; r += 32)
                if (r >= j) colc[r] -= w * colj[r];
        }
        __syncthreads();
    }

    for (int i = 63; i >= 0; i--) {
        float* coli = sA + i * 257;
        float tau = s_tau[i];
        for (int c = i + 1 + warp; c < 64; c += 8) {
            float* colc = sA + c * 257;
            float dt = 0.f;
            for (int r = lane; r < 256; r += 32)
                if (r >= i) dt += coli[r] * colc[r];
#pragma unroll
            for (int o = 16; o > 0; o >>= 1) dt += __shfl_xor_sync(0xffffffffu, dt, o);
            float w = tau * dt;
            for (int r = lane; r < 256; r += 32)
                if (r >= i) colc[r] -= w * coli[r];
        }
        __syncthreads();
        float v = coli[tid];
        float nv;
        if (tid < i)       nv = 0.f;
        else if (tid == i) nv = 1.f - tau;
        else               nv = -tau * v;
        coli[tid] = nv;
        __syncthreads();
    }

    for (int idx = tid; idx < NN * DD; idx += 256) {
        int r = idx >> 6, c = idx & 63;
        dst[(size_t)(b * 256 + r) * 768 + h * 64 + c] = sA[c * 257 + r];
    }
}

// =====================================================================
// Fused channel-mix (12x12 over duplicated 2H concat) + softmax.
// Block per (b, n): 384 threads = 12 warps, warp o handles channel o.
// =====================================================================
__global__ void mixsoftmax_kernel(const float* __restrict__ conv_w,
                                  const float* __restrict__ conv_b)
{
    __shared__ float s_sq[12][256];
    __shared__ float s_w2[12][12];
    __shared__ float s_cb[12];

    int tid = threadIdx.x;
    int n = blockIdx.x, b = blockIdx.y;

    if (tid < 144) {
        int o = tid / 12, h = tid % 12;
        s_w2[o][h] = conv_w[o * 24 + h] + conv_w[o * 24 + 12 + h];
    }
    if (tid < 12) s_cb[tid] = conv_b[tid];
    for (int idx = tid; idx < 3072; idx += 384) {
        int h = idx >> 8, m = idx & 255;
        s_sq[h][m] = g_sq[(((size_t)(b * 12 + h) * 256) + n) * 256 + m];
    }
    __syncthreads();

    int o = tid >> 5, lane = tid & 31;
    float v[8];
    float mx = -1e30f;
#pragma unroll
    for (int i = 0; i < 8; i++) {
        int m = i * 32 + lane;
        float acc = s_cb[o];
#pragma unroll
        for (int h = 0; h < 12; h++) acc += s_w2[o][h] * s_sq[h][m];
        v[i] = acc;
        mx = fmaxf(mx, acc);
    }
#pragma unroll
    for (int off = 16; off > 0; off >>= 1) mx = fmaxf(mx, __shfl_xor_sync(0xffffffffu, mx, off));
    float sm = 0.f;
#pragma unroll
    for (int i = 0; i < 8; i++) { v[i] = expf(v[i] - mx); sm += v[i]; }
#pragma unroll
    for (int off = 16; off > 0; off >>= 1) sm += __shfl_xor_sync(0xffffffffu, sm, off);
    float inv = 1.f / sm;
    float* dst = g_mix + (((size_t)(b * 12 + o) * 256) + n) * 256;
#pragma unroll
    for (int i = 0; i < 8; i++) dst[i * 32 + lane] = v[i] * inv;
}

// =====================================================================
extern "C" void kernel_launch(void* const* d_in, const int* in_sizes, int n_in,
                              void* d_out, int out_size)
{
    const float* x      = (const float*)d_in[0];
    const float* qkv_w  = (const float*)d_in[1];
    const float* qkv_b  = (const float*)d_in[2];
    const float* gscale = (const float*)d_in[3];
    const float* conv_w = (const float*)d_in[4];
    const float* conv_b = (const float*)d_in[5];
    const float* proj_w = (const float*)d_in[6];
    const float* proj_b = (const float*)d_in[7];
    float* out = (float*)d_out;

    cudaFuncSetAttribute(qr_kernel, cudaFuncAttributeMaxDynamicSharedMemorySize, 64 * 257 * 4);

    // 1) QKV projection + scatter  (M=8192, N=2304, K=768)
    gemm_mma<0, 128, 48><<<dim3(18, 64), 256>>>(x, qkv_w, qkv_b, nullptr);
    // 2) batched Householder QR (768 slabs of 256x64)
    qr_kernel<<<768, 256, 64 * 257 * 4>>>();
    // 3) Grassmann dots, squared+scaled  (per (b,h): 256x256x64)
    gemm_mma<1, 128, 4><<<dim3(4, 12, 32), 256>>>(nullptr, nullptr, gscale, nullptr);
    // 4) channel mix + softmax
    mixsoftmax_kernel<<<dim3(256, 32), 384>>>(conv_w, conv_b);
    // 5) PV  (per (b,h): 256x64x256)
    gemm_mma<2, 64, 16><<<dim3(2, 384), 256>>>(nullptr, nullptr, nullptr, nullptr);
    // 6) output projection (M=8192, N=768, K=768)
    gemm_mma<3, 128, 48><<<dim3(6, 64), 256>>>(nullptr, proj_w, proj_b, out);
}